// round 16
// baseline (speedup 1.0000x reference)
#include <cuda_runtime.h>
#include <cuda_bf16.h>
#include <cfloat>
#include <cstdint>

namespace {
constexpr int kB  = 2;
constexpr int kH  = 8;
constexpr int kS  = 2048;
constexpr int kDK = 32;
constexpr int kDM = 256;
constexpr int kNRow = kB * kS;           // 4096
constexpr float kScale = 0.17677669529663687f;  // 1/sqrt(32)
constexpr int kCap = 128;                // candidate cap per query row
constexpr int kKC  = 64;                 // cat K: [hi(32) | lo(32)] bf16
constexpr int kIT  = 64;                 // fused CTA i-tile (query rows)
constexpr int kNJ  = kS / 128;           // 16 B tiles per row

// fused-kernel smem layout (bytes)
constexpr int kOffA   = 0;                       // 64 x 128B = 8 KB
constexpr int kOffB0  = kOffA + kIT * 128;       // 16 KB
constexpr int kOffB1  = kOffB0 + 128 * 128;      // 16 KB
constexpr int kOffLst = kOffB1 + 128 * 128;      // 64*128*8 = 64 KB
constexpr int kOffMax = kOffLst + kIT * kCap * 8;
constexpr int kOffCnt = kOffMax + kIT * 4;
constexpr int kOffThr = kOffCnt + kIT * 4;
constexpr int kSmemFused = kOffThr + kIT * 4;    // ~105.3 KB
}

// Scratch buffers (all L2-resident: 4 MB each).
__device__ float g_v[kB * kH * kS * kDK];                 // V fp32
__device__ __nv_bfloat16 g_qcat[kB * kH * kS * kKC];      // [Qhi*scale | Qlo*scale]
__device__ __nv_bfloat16 g_kcat[kB * kH * kS * kKC];      // [Khi | Klo]

// ---------------------------------------------------------------------------
// Helpers
// ---------------------------------------------------------------------------
__device__ __forceinline__ uint32_t smem_u32(const void* p) {
    uint32_t a;
    asm("{ .reg .u64 t; cvta.to.shared.u64 t, %1; cvt.u32.u64 %0, t; }"
        : "=r"(a) : "l"(p));
    return a;
}
__device__ __forceinline__ void ldsm_x4(uint32_t* r, uint32_t addr) {
    asm volatile("ldmatrix.sync.aligned.m8n8.x4.shared.b16 {%0,%1,%2,%3}, [%4];"
                 : "=r"(r[0]), "=r"(r[1]), "=r"(r[2]), "=r"(r[3]) : "r"(addr));
}
__device__ __forceinline__ void mma_bf16(float* d, const uint32_t* a, const uint32_t* b) {
    asm volatile(
        "mma.sync.aligned.m16n8k16.row.col.f32.bf16.bf16.f32 "
        "{%0,%1,%2,%3}, {%4,%5,%6,%7}, {%8,%9}, {%0,%1,%2,%3};"
        : "+f"(d[0]), "+f"(d[1]), "+f"(d[2]), "+f"(d[3])
        : "r"(a[0]), "r"(a[1]), "r"(a[2]), "r"(a[3]), "r"(b[0]), "r"(b[1]));
}
__device__ __forceinline__ void cp_async16(uint32_t smem_addr, const void* gmem) {
    asm volatile("cp.async.cg.shared.global [%0], [%1], 16;"
                 :: "r"(smem_addr), "l"(gmem) : "memory");
}
__device__ __forceinline__ void cp_commit() {
    asm volatile("cp.async.commit_group;" ::: "memory");
}
__device__ __forceinline__ void cp_wait_all() {
    asm volatile("cp.async.wait_group 0;" ::: "memory");
}
__device__ __forceinline__ uint32_t fenc(float f) {        // monotone float->uint
    uint32_t u = __float_as_uint(f);
    return (u & 0x80000000u) ? ~u : (u | 0x80000000u);
}
__device__ __forceinline__ float fdec(uint32_t u) {
    return __uint_as_float((u & 0x80000000u) ? (u & 0x7FFFFFFFu) : ~u);
}
#define SW128(off) ((off) ^ (((off) >> 3) & 0x70))

// ---------------------------------------------------------------------------
// Kernel 1 — projection GEMM; epilogue emits V fp32 and bf16 hi/lo cat
// buffers (Q pre-scaled by 1/sqrt(dk)).  (unchanged, ~58 us)
// ---------------------------------------------------------------------------
__global__ __launch_bounds__(256)
void proj_kernel(const float* __restrict__ xq, const float* __restrict__ xk,
                 const float* __restrict__ xv,
                 const float* __restrict__ wq, const float* __restrict__ bq,
                 const float* __restrict__ wk, const float* __restrict__ bk,
                 const float* __restrict__ wv, const float* __restrict__ bv)
{
    constexpr int PBM = 128, PBN = 64, PBK = 16;
    __shared__ float As[PBK][PBM];
    __shared__ float Bs[PBK][PBN];

    const int z = blockIdx.z;
    const float* __restrict__ X    = (z == 0) ? xq : (z == 1) ? xk : xv;
    const float* __restrict__ W    = (z == 0) ? wq : (z == 1) ? wk : wv;
    const float* __restrict__ bias = (z == 0) ? bq : (z == 1) ? bk : bv;

    const int n0 = blockIdx.y * PBM;
    const int c0 = blockIdx.x * PBN;
    const int tid = threadIdx.x;
    const int tx = tid & 15;
    const int ty = tid >> 4;

    float acc[8][4];
    #pragma unroll
    for (int i = 0; i < 8; ++i)
        #pragma unroll
        for (int j = 0; j < 4; ++j) acc[i][j] = 0.0f;

    for (int k0 = 0; k0 < kDM; k0 += PBK) {
        #pragma unroll
        for (int r = 0; r < 2; ++r) {
            int f   = tid + r * 256;
            int row = f >> 2;
            int kk  = (f & 3) * 4;
            float4 v = *reinterpret_cast<const float4*>(X + (n0 + row) * kDM + k0 + kk);
            As[kk + 0][row] = v.x; As[kk + 1][row] = v.y;
            As[kk + 2][row] = v.z; As[kk + 3][row] = v.w;
        }
        {
            int n  = tid >> 2;
            int kk = (tid & 3) * 4;
            float4 v = *reinterpret_cast<const float4*>(W + (c0 + n) * kDM + k0 + kk);
            Bs[kk + 0][n] = v.x; Bs[kk + 1][n] = v.y;
            Bs[kk + 2][n] = v.z; Bs[kk + 3][n] = v.w;
        }
        __syncthreads();

        #pragma unroll
        for (int k = 0; k < PBK; ++k) {
            float4 a0 = *reinterpret_cast<const float4*>(&As[k][ty * 8]);
            float4 a1 = *reinterpret_cast<const float4*>(&As[k][ty * 8 + 4]);
            float4 bb = *reinterpret_cast<const float4*>(&Bs[k][tx * 4]);
            float a[8] = {a0.x, a0.y, a0.z, a0.w, a1.x, a1.y, a1.z, a1.w};
            float b[4] = {bb.x, bb.y, bb.z, bb.w};
            #pragma unroll
            for (int i = 0; i < 8; ++i)
                #pragma unroll
                for (int j = 0; j < 4; ++j)
                    acc[i][j] = fmaf(a[i], b[j], acc[i][j]);
        }
        __syncthreads();
    }

    #pragma unroll
    for (int i = 0; i < 8; ++i) {
        const int row = n0 + ty * 8 + i;
        const int bb  = row / kS;
        const int ss  = row % kS;
        #pragma unroll
        for (int j = 0; j < 4; ++j) {
            const int col = c0 + tx * 4 + j;
            const int h = col >> 5, d = col & 31;
            const int r = (bb * kH + h) * kS + ss;
            float val = acc[i][j] + bias[col];
            if (z == 2) {
                g_v[r * kDK + d] = val;
            } else {
                if (z == 0) val *= kScale;           // pre-scale Q
                __nv_bfloat16 hi = __float2bfloat16(val);
                __nv_bfloat16 lo = __float2bfloat16(val - __bfloat162float(hi));
                __nv_bfloat16* dst = (z == 0) ? g_qcat : g_kcat;
                dst[r * kKC + d]       = hi;
                dst[r * kKC + 32 + d]  = lo;
            }
        }
    }
}

// ---------------------------------------------------------------------------
// Exact fallback for candidate-list overflow (~never): recompute row scores
// from qcat/kcat fp32 (hi+lo), Michelot + ballot-pop AV.
// ---------------------------------------------------------------------------
__device__ __noinline__ float slow_row_qk(int bh, int qi, float tau0,
                                          const float* __restrict__ Vbh, int lane)
{
    const __nv_bfloat16* __restrict__ Qr = g_qcat + ((size_t)bh * kS + qi) * kKC;
    const __nv_bfloat16* __restrict__ Kb = g_kcat + (size_t)bh * kS * kKC;
    float q[kDK];
    #pragma unroll
    for (int d = 0; d < kDK; ++d)
        q[d] = __bfloat162float(Qr[d]) + __bfloat162float(Qr[32 + d]);

    float tau = tau0;
    int prev = -1;
    for (int it = 0; it < 60; ++it) {
        float sum = 0.0f; int c = 0;
        for (int j = lane; j < kS; j += 32) {
            const __nv_bfloat16* kr = Kb + (size_t)j * kKC;
            float s = 0.0f;
            #pragma unroll
            for (int d = 0; d < kDK; ++d)
                s = fmaf(q[d], __bfloat162float(kr[d]) + __bfloat162float(kr[32 + d]), s);
            if (s > tau) { sum += s; ++c; }
        }
        #pragma unroll
        for (int o = 16; o; o >>= 1) {
            sum += __shfl_xor_sync(0xffffffffu, sum, o);
            c   += __shfl_xor_sync(0xffffffffu, c, o);
        }
        if (c == prev || c == 0) break;
        tau = (sum - 1.0f) / (float)c;
        prev = c;
    }
    float a = 0.0f;
    for (int j = lane; j < kS; j += 32) {
        const __nv_bfloat16* kr = Kb + (size_t)j * kKC;
        float s = 0.0f;
        #pragma unroll
        for (int d = 0; d < kDK; ++d)
            s = fmaf(q[d], __bfloat162float(kr[d]) + __bfloat162float(kr[32 + d]), s);
        float w = s - tau;
        unsigned mk = __ballot_sync(0xffffffffu, w > 0.0f);
        while (mk) {
            int b = __ffs(mk) - 1;
            mk &= mk - 1;
            float wb = __shfl_sync(0xffffffffu, w, b);
            int jj = __shfl_sync(0xffffffffu, j, b);
            a = fmaf(wb, __ldg(Vbh + jj * kDK + lane), a);
        }
    }
    return a;
}

// ---------------------------------------------------------------------------
// Kernel 2 — FUSED attention: two HMMA passes + in-kernel sparsemax/AV.
// CTA = 64 query rows x all 2048 keys. A staged once; B double-buffered
// cp.async (kcat is L2-resident). Pass 1: exact row max (regs + smem
// atomicMax). Pass 2: recompute scores, append s > m-1 to smem lists.
// Finalize: 1 warp/row Michelot + sparse AV. No dense score store at all.
// ---------------------------------------------------------------------------
__global__ __launch_bounds__(256, 2)
void attn_fused(float* __restrict__ out)
{
    extern __shared__ __align__(128) char smem[];
    const uint32_t sAu = smem_u32(smem + kOffA);
    const uint32_t sBu[2] = {smem_u32(smem + kOffB0), smem_u32(smem + kOffB1)};
    float2*   __restrict__ Lists = reinterpret_cast<float2*>(smem + kOffLst);
    uint32_t* __restrict__ Maxu  = reinterpret_cast<uint32_t*>(smem + kOffMax);
    uint32_t* __restrict__ Cnt   = reinterpret_cast<uint32_t*>(smem + kOffCnt);
    float*    __restrict__ Thr   = reinterpret_cast<float*>(smem + kOffThr);

    const int bh = blockIdx.y;
    const int i0 = blockIdx.x * kIT;
    const int tid  = threadIdx.x;
    const int wid  = tid >> 5;
    const int lane = tid & 31;

    const uint4* __restrict__ Ag = reinterpret_cast<const uint4*>(
        g_qcat + ((size_t)bh * kS + i0) * kKC);
    const uint4* __restrict__ Kg = reinterpret_cast<const uint4*>(
        g_kcat + (size_t)bh * kS * kKC);

    if (tid < kIT) Maxu[tid] = 0u;      // encodes below -FLT_MAX

    // Stage A (64 rows) + B tile 0
    #pragma unroll
    for (int r = 0; r < 2; ++r) {
        const int f = tid + r * 256;    // 0..511
        const int row = f >> 3, c16 = f & 7;
        cp_async16(sAu + SW128((uint32_t)(row * 128 + c16 * 16)), Ag + row * 8 + c16);
    }
    #pragma unroll
    for (int r = 0; r < 4; ++r) {
        const int f = tid + r * 256;    // 0..1023
        const int row = f >> 3, c16 = f & 7;
        cp_async16(sBu[0] + SW128((uint32_t)(row * 128 + c16 * 16)), Kg + row * 8 + c16);
    }
    cp_commit();
    cp_wait_all();
    __syncthreads();

    // Warp layout: 2(m) x 4(n); warp tile 32 rows x 32 cols of each 128-tile.
    const int wm = wid & 1;
    const int wn = wid >> 1;
    const int imb = wm * 32;
    const int jnb = wn * 32;
    const int g  = lane >> 2;
    const int tg = lane & 3;

    // ---------------- PASS 1: exact row max ----------------
    float rmax[2][2];
    rmax[0][0] = rmax[0][1] = rmax[1][0] = rmax[1][1] = -FLT_MAX;

    #pragma unroll 1
    for (int jt = 0; jt < kNJ; ++jt) {
        const int cur = jt & 1;
        if (jt + 1 < kNJ) {
            #pragma unroll
            for (int r = 0; r < 4; ++r) {
                const int f = tid + r * 256;
                const int row = f >> 3, c16 = f & 7;
                cp_async16(sBu[cur ^ 1] + SW128((uint32_t)(row * 128 + c16 * 16)),
                           Kg + (size_t)((jt + 1) * 128 + row) * 8 + c16);
            }
            cp_commit();
        }

        float acc[2][4][4];
        #pragma unroll
        for (int mt = 0; mt < 2; ++mt)
            #pragma unroll
            for (int nt = 0; nt < 4; ++nt)
                #pragma unroll
                for (int e = 0; e < 4; ++e) acc[mt][nt][e] = 0.0f;

        #pragma unroll
        for (int kk = 0; kk < 32; kk += 16) {
            uint32_t afh[2][4], afl[2][4];
            #pragma unroll
            for (int mt = 0; mt < 2; ++mt) {
                const int row = imb + mt * 16 + (lane & 15);
                const int chkh = (kk >> 3) + (lane >> 4);
                const int chkl = ((kk + 32) >> 3) + (lane >> 4);
                ldsm_x4(afh[mt], sAu + SW128((uint32_t)(row * 128 + chkh * 16)));
                ldsm_x4(afl[mt], sAu + SW128((uint32_t)(row * 128 + chkl * 16)));
            }
            uint32_t bfh[4][2], bfl[4][2];
            #pragma unroll
            for (int np = 0; np < 2; ++np) {
                const int row = jnb + np * 16 + (lane & 7) + ((lane & 16) >> 1);
                const int chkh = (kk >> 3) + ((lane >> 3) & 1);
                const int chkl = ((kk + 32) >> 3) + ((lane >> 3) & 1);
                uint32_t r4[4];
                ldsm_x4(r4, sBu[cur] + SW128((uint32_t)(row * 128 + chkh * 16)));
                bfh[np * 2 + 0][0] = r4[0]; bfh[np * 2 + 0][1] = r4[1];
                bfh[np * 2 + 1][0] = r4[2]; bfh[np * 2 + 1][1] = r4[3];
                ldsm_x4(r4, sBu[cur] + SW128((uint32_t)(row * 128 + chkl * 16)));
                bfl[np * 2 + 0][0] = r4[0]; bfl[np * 2 + 0][1] = r4[1];
                bfl[np * 2 + 1][0] = r4[2]; bfl[np * 2 + 1][1] = r4[3];
            }
            #pragma unroll
            for (int mt = 0; mt < 2; ++mt)
                #pragma unroll
                for (int nt = 0; nt < 4; ++nt) {
                    float* a = acc[mt][nt];
                    mma_bf16(a, afh[mt], bfh[nt]);   // hi.hi
                    mma_bf16(a, afl[mt], bfh[nt]);   // lo.hi
                    mma_bf16(a, afh[mt], bfl[nt]);   // hi.lo
                }
        }

        #pragma unroll
        for (int mt = 0; mt < 2; ++mt)
            #pragma unroll
            for (int nt = 0; nt < 4; ++nt) {
                rmax[mt][0] = fmaxf(rmax[mt][0], fmaxf(acc[mt][nt][0], acc[mt][nt][1]));
                rmax[mt][1] = fmaxf(rmax[mt][1], fmaxf(acc[mt][nt][2], acc[mt][nt][3]));
            }

        if (jt + 1 < kNJ) cp_wait_all();
        __syncthreads();
    }

    // Reduce rmax over tg lanes, atomicMax into smem per-row slots.
    #pragma unroll
    for (int mt = 0; mt < 2; ++mt)
        #pragma unroll
        for (int hf = 0; hf < 2; ++hf) {
            float v = rmax[mt][hf];
            v = fmaxf(v, __shfl_xor_sync(0xffffffffu, v, 1));
            v = fmaxf(v, __shfl_xor_sync(0xffffffffu, v, 2));
            if (tg == 0)
                atomicMax(&Maxu[imb + mt * 16 + hf * 8 + g], fenc(v));
        }

    // Prime pass-2 B tile 0 while thresholds settle.
    #pragma unroll
    for (int r = 0; r < 4; ++r) {
        const int f = tid + r * 256;
        const int row = f >> 3, c16 = f & 7;
        cp_async16(sBu[0] + SW128((uint32_t)(row * 128 + c16 * 16)), Kg + row * 8 + c16);
    }
    cp_commit();
    __syncthreads();
    if (tid < kIT) {
        Thr[tid] = fdec(Maxu[tid]) - 1.0f;
        Cnt[tid] = 0u;
    }
    cp_wait_all();
    __syncthreads();

    // ---------------- PASS 2: candidate compaction ----------------
    #pragma unroll 1
    for (int jt = 0; jt < kNJ; ++jt) {
        const int cur = jt & 1;
        if (jt + 1 < kNJ) {
            #pragma unroll
            for (int r = 0; r < 4; ++r) {
                const int f = tid + r * 256;
                const int row = f >> 3, c16 = f & 7;
                cp_async16(sBu[cur ^ 1] + SW128((uint32_t)(row * 128 + c16 * 16)),
                           Kg + (size_t)((jt + 1) * 128 + row) * 8 + c16);
            }
            cp_commit();
        }

        float acc[2][4][4];
        #pragma unroll
        for (int mt = 0; mt < 2; ++mt)
            #pragma unroll
            for (int nt = 0; nt < 4; ++nt)
                #pragma unroll
                for (int e = 0; e < 4; ++e) acc[mt][nt][e] = 0.0f;

        #pragma unroll
        for (int kk = 0; kk < 32; kk += 16) {
            uint32_t afh[2][4], afl[2][4];
            #pragma unroll
            for (int mt = 0; mt < 2; ++mt) {
                const int row = imb + mt * 16 + (lane & 15);
                const int chkh = (kk >> 3) + (lane >> 4);
                const int chkl = ((kk + 32) >> 3) + (lane >> 4);
                ldsm_x4(afh[mt], sAu + SW128((uint32_t)(row * 128 + chkh * 16)));
                ldsm_x4(afl[mt], sAu + SW128((uint32_t)(row * 128 + chkl * 16)));
            }
            uint32_t bfh[4][2], bfl[4][2];
            #pragma unroll
            for (int np = 0; np < 2; ++np) {
                const int row = jnb + np * 16 + (lane & 7) + ((lane & 16) >> 1);
                const int chkh = (kk >> 3) + ((lane >> 3) & 1);
                const int chkl = ((kk + 32) >> 3) + ((lane >> 3) & 1);
                uint32_t r4[4];
                ldsm_x4(r4, sBu[cur] + SW128((uint32_t)(row * 128 + chkh * 16)));
                bfh[np * 2 + 0][0] = r4[0]; bfh[np * 2 + 0][1] = r4[1];
                bfh[np * 2 + 1][0] = r4[2]; bfh[np * 2 + 1][1] = r4[3];
                ldsm_x4(r4, sBu[cur] + SW128((uint32_t)(row * 128 + chkl * 16)));
                bfl[np * 2 + 0][0] = r4[0]; bfl[np * 2 + 0][1] = r4[1];
                bfl[np * 2 + 1][0] = r4[2]; bfl[np * 2 + 1][1] = r4[3];
            }
            #pragma unroll
            for (int mt = 0; mt < 2; ++mt)
                #pragma unroll
                for (int nt = 0; nt < 4; ++nt) {
                    float* a = acc[mt][nt];
                    mma_bf16(a, afh[mt], bfh[nt]);
                    mma_bf16(a, afl[mt], bfh[nt]);
                    mma_bf16(a, afh[mt], bfl[nt]);
                }
        }

        // Candidate append: s > Thr[row] -> smem list.
        #pragma unroll
        for (int mt = 0; mt < 2; ++mt) {
            const int r0 = imb + mt * 16 + g;
            const float t0 = Thr[r0];
            const float t1 = Thr[r0 + 8];
            #pragma unroll
            for (int nt = 0; nt < 4; ++nt) {
                const int colb = jt * 128 + jnb + nt * 8 + tg * 2;
                #pragma unroll
                for (int e = 0; e < 4; ++e) {
                    const float v = acc[mt][nt][e];
                    const int  row = (e < 2) ? r0 : r0 + 8;
                    const float t  = (e < 2) ? t0 : t1;
                    if (v > t) {
                        unsigned idx = atomicAdd(&Cnt[row], 1u);
                        if (idx < (unsigned)kCap)
                            Lists[row * kCap + idx] =
                                make_float2(v, __int_as_float(colb + (e & 1)));
                    }
                }
            }
        }

        if (jt + 1 < kNJ) cp_wait_all();
        __syncthreads();
    }

    // ---------------- FINALIZE: 1 warp per row ----------------
    const float* __restrict__ Vbh = g_v + bh * kS * kDK;
    const int bb = bh >> 3;
    const int h  = bh & 7;

    #pragma unroll 1
    for (int rr = 0; rr < kIT / 8; ++rr) {
        const int row = wid * 8 + rr;
        const int n = (int)Cnt[row];
        const float thr = Thr[row];
        const float2* __restrict__ Lq = Lists + row * kCap;
        float a;
        if (n <= kCap) {
            float c0 = (lane      < n) ? Lq[lane     ].x : -FLT_MAX;
            float c1 = (lane + 32 < n) ? Lq[lane + 32].x : -FLT_MAX;
            float c2 = (lane + 64 < n) ? Lq[lane + 64].x : -FLT_MAX;
            float c3 = (lane + 96 < n) ? Lq[lane + 96].x : -FLT_MAX;
            float tau = thr;
            int prev = -1;
            for (int it = 0; it < 80; ++it) {
                float sum = 0.0f; int cnt = 0;
                if (c0 > tau) { sum += c0; ++cnt; }
                if (c1 > tau) { sum += c1; ++cnt; }
                if (c2 > tau) { sum += c2; ++cnt; }
                if (c3 > tau) { sum += c3; ++cnt; }
                #pragma unroll
                for (int o = 16; o; o >>= 1) {
                    sum += __shfl_xor_sync(0xffffffffu, sum, o);
                    cnt += __shfl_xor_sync(0xffffffffu, cnt, o);
                }
                if (cnt == prev || cnt == 0) break;
                tau = (sum - 1.0f) / (float)cnt;
                prev = cnt;
            }
            float a0 = 0.0f, a1 = 0.0f;
            int ci = 0;
            for (; ci + 2 <= n; ci += 2) {
                float2 p0 = Lq[ci], p1 = Lq[ci + 1];
                float w0 = fmaxf(p0.x - tau, 0.0f);
                float w1 = fmaxf(p1.x - tau, 0.0f);
                a0 = fmaf(w0, __ldg(Vbh + __float_as_int(p0.y) * kDK + lane), a0);
                a1 = fmaf(w1, __ldg(Vbh + __float_as_int(p1.y) * kDK + lane), a1);
            }
            if (ci < n) {
                float2 p = Lq[ci];
                float w = fmaxf(p.x - tau, 0.0f);
                a0 = fmaf(w, __ldg(Vbh + __float_as_int(p.y) * kDK + lane), a0);
            }
            a = a0 + a1;
        } else {
            a = slow_row_qk(bh, i0 + row, thr, Vbh, lane);
        }
        out[(bb * kS + (i0 + row)) * kDM + h * kDK + lane] = a;
    }
}

// ---------------------------------------------------------------------------
extern "C" void kernel_launch(void* const* d_in, const int* in_sizes, int n_in,
                              void* d_out, int out_size)
{
    const float* query = (const float*)d_in[0];
    const float* key   = (const float*)d_in[1];
    const float* value = (const float*)d_in[2];
    const float* Wq    = (const float*)d_in[3];
    const float* bq    = (const float*)d_in[4];
    const float* Wk    = (const float*)d_in[5];
    const float* bk    = (const float*)d_in[6];
    const float* Wv    = (const float*)d_in[7];
    const float* bv    = (const float*)d_in[8];
    float* out = (float*)d_out;

    dim3 pgrid(kDM / 64, kNRow / 128, 3);      // (4, 32, 3)
    proj_kernel<<<pgrid, 256>>>(query, key, value, Wq, bq, Wk, bk, Wv, bv);

    cudaFuncSetAttribute(attn_fused,
                         cudaFuncAttributeMaxDynamicSharedMemorySize, kSmemFused);
    dim3 agrid(kS / kIT, kB * kH);             // (32, 16) = 512 CTAs
    attn_fused<<<agrid, 256, kSmemFused>>>(out);

    (void)in_sizes; (void)n_in; (void)out_size;
}

// round 17
// speedup vs baseline: 6.5757x; 6.5757x over previous
#include <cuda_runtime.h>
#include <cuda_bf16.h>
#include <cfloat>
#include <cstdint>

namespace {
constexpr int kB  = 2;
constexpr int kH  = 8;
constexpr int kS  = 2048;
constexpr int kDK = 32;
constexpr int kDM = 256;
constexpr int kNRow = kB * kS;           // 4096
constexpr float kScale = 0.17677669529663687f;  // 1/sqrt(32)
constexpr int kCap = 128;                // candidate cap per query row
constexpr int kKC  = 64;                 // cat K: [hi(32) | lo(32)] bf16
constexpr int kNT  = kS / 128;           // 16 column tiles per row
constexpr int kTileB = 128 * 128;        // 16 KB tile
constexpr int kSmemScore = kTileB * 4;   // A + 3x B buffers = 64 KB
}

// Scratch buffers.
__device__ float g_v[kB * kH * kS * kDK];                 // V fp32
__device__ __nv_bfloat16 g_qcat[kB * kH * kS * kKC];      // [Qhi*scale | Qlo*scale]
__device__ __nv_bfloat16 g_kcat[kB * kH * kS * kKC];      // [Khi | Klo]
__device__ float g_s[(size_t)kB * kH * kS * kS];          // scores (256 MiB)
__device__ float g_tmax2[(size_t)kB * kH * kS * kNT * 2]; // per-row per-tile max, 2 slots

// ---------------------------------------------------------------------------
// Helpers
// ---------------------------------------------------------------------------
__device__ __forceinline__ uint32_t smem_u32(const void* p) {
    uint32_t a;
    asm("{ .reg .u64 t; cvta.to.shared.u64 t, %1; cvt.u32.u64 %0, t; }"
        : "=r"(a) : "l"(p));
    return a;
}
__device__ __forceinline__ void ldsm_x4(uint32_t* r, uint32_t addr) {
    asm volatile("ldmatrix.sync.aligned.m8n8.x4.shared.b16 {%0,%1,%2,%3}, [%4];"
                 : "=r"(r[0]), "=r"(r[1]), "=r"(r[2]), "=r"(r[3]) : "r"(addr));
}
__device__ __forceinline__ void mma_bf16(float* d, const uint32_t* a, const uint32_t* b) {
    asm volatile(
        "mma.sync.aligned.m16n8k16.row.col.f32.bf16.bf16.f32 "
        "{%0,%1,%2,%3}, {%4,%5,%6,%7}, {%8,%9}, {%0,%1,%2,%3};"
        : "+f"(d[0]), "+f"(d[1]), "+f"(d[2]), "+f"(d[3])
        : "r"(a[0]), "r"(a[1]), "r"(a[2]), "r"(a[3]), "r"(b[0]), "r"(b[1]));
}
__device__ __forceinline__ void cp_async16(uint32_t smem_addr, const void* gmem) {
    asm volatile("cp.async.cg.shared.global [%0], [%1], 16;"
                 :: "r"(smem_addr), "l"(gmem) : "memory");
}
__device__ __forceinline__ void cp_commit() {
    asm volatile("cp.async.commit_group;" ::: "memory");
}
template <int N>
__device__ __forceinline__ void cp_wait_group() {
    asm volatile("cp.async.wait_group %0;" :: "n"(N) : "memory");
}
#define SW128(off) ((off) ^ (((off) >> 3) & 0x70))

// ---------------------------------------------------------------------------
// Kernel 1 — projection GEMM; epilogue emits V fp32 and bf16 hi/lo cat
// buffers (Q pre-scaled by 1/sqrt(dk)).  (unchanged)
// ---------------------------------------------------------------------------
__global__ __launch_bounds__(256)
void proj_kernel(const float* __restrict__ xq, const float* __restrict__ xk,
                 const float* __restrict__ xv,
                 const float* __restrict__ wq, const float* __restrict__ bq,
                 const float* __restrict__ wk, const float* __restrict__ bk,
                 const float* __restrict__ wv, const float* __restrict__ bv)
{
    constexpr int PBM = 128, PBN = 64, PBK = 16;
    __shared__ float As[PBK][PBM];
    __shared__ float Bs[PBK][PBN];

    const int z = blockIdx.z;
    const float* __restrict__ X    = (z == 0) ? xq : (z == 1) ? xk : xv;
    const float* __restrict__ W    = (z == 0) ? wq : (z == 1) ? wk : wv;
    const float* __restrict__ bias = (z == 0) ? bq : (z == 1) ? bk : bv;

    const int n0 = blockIdx.y * PBM;
    const int c0 = blockIdx.x * PBN;
    const int tid = threadIdx.x;
    const int tx = tid & 15;
    const int ty = tid >> 4;

    float acc[8][4];
    #pragma unroll
    for (int i = 0; i < 8; ++i)
        #pragma unroll
        for (int j = 0; j < 4; ++j) acc[i][j] = 0.0f;

    for (int k0 = 0; k0 < kDM; k0 += PBK) {
        #pragma unroll
        for (int r = 0; r < 2; ++r) {
            int f   = tid + r * 256;
            int row = f >> 2;
            int kk  = (f & 3) * 4;
            float4 v = *reinterpret_cast<const float4*>(X + (n0 + row) * kDM + k0 + kk);
            As[kk + 0][row] = v.x; As[kk + 1][row] = v.y;
            As[kk + 2][row] = v.z; As[kk + 3][row] = v.w;
        }
        {
            int n  = tid >> 2;
            int kk = (tid & 3) * 4;
            float4 v = *reinterpret_cast<const float4*>(W + (c0 + n) * kDM + k0 + kk);
            Bs[kk + 0][n] = v.x; Bs[kk + 1][n] = v.y;
            Bs[kk + 2][n] = v.z; Bs[kk + 3][n] = v.w;
        }
        __syncthreads();

        #pragma unroll
        for (int k = 0; k < PBK; ++k) {
            float4 a0 = *reinterpret_cast<const float4*>(&As[k][ty * 8]);
            float4 a1 = *reinterpret_cast<const float4*>(&As[k][ty * 8 + 4]);
            float4 bb = *reinterpret_cast<const float4*>(&Bs[k][tx * 4]);
            float a[8] = {a0.x, a0.y, a0.z, a0.w, a1.x, a1.y, a1.z, a1.w};
            float b[4] = {bb.x, bb.y, bb.z, bb.w};
            #pragma unroll
            for (int i = 0; i < 8; ++i)
                #pragma unroll
                for (int j = 0; j < 4; ++j)
                    acc[i][j] = fmaf(a[i], b[j], acc[i][j]);
        }
        __syncthreads();
    }

    #pragma unroll
    for (int i = 0; i < 8; ++i) {
        const int row = n0 + ty * 8 + i;
        const int bb  = row / kS;
        const int ss  = row % kS;
        #pragma unroll
        for (int j = 0; j < 4; ++j) {
            const int col = c0 + tx * 4 + j;
            const int h = col >> 5, d = col & 31;
            const int r = (bb * kH + h) * kS + ss;
            float val = acc[i][j] + bias[col];
            if (z == 2) {
                g_v[r * kDK + d] = val;
            } else {
                if (z == 0) val *= kScale;           // pre-scale Q
                __nv_bfloat16 hi = __float2bfloat16(val);
                __nv_bfloat16 lo = __float2bfloat16(val - __bfloat162float(hi));
                __nv_bfloat16* dst = (z == 0) ? g_qcat : g_kcat;
                dst[r * kKC + d]       = hi;
                dst[r * kKC + 32 + d]  = lo;
            }
        }
    }
}

// ---------------------------------------------------------------------------
// Kernel 2 — score GEMM on mma.sync bf16 (hi/lo split, fp32 accumulate).
// S = Qhi.Khi + Qlo.Khi + Qhi.Klo (lo.lo dropped, <=2^-16 rel).
// Each CTA: one 128-row A tile staged ONCE, then all 16 j-tiles with a
// 2-deep (3-buffer) cp.async pipeline overlapping B staging with
// MMA + epilogue. 8 warps as 4(m) x 2(n); warp tile 32x64.
// ---------------------------------------------------------------------------
__global__ __launch_bounds__(256, 2)
void score_gemm_tc(void)
{
    extern __shared__ __align__(128) char smem[];
    const uint32_t sAu = smem_u32(smem);
    const uint32_t sBu[3] = {smem_u32(smem + kTileB),
                             smem_u32(smem + 2 * kTileB),
                             smem_u32(smem + 3 * kTileB)};

    const int bh = blockIdx.z;
    const int i0 = blockIdx.y * 128;
    const int tid  = threadIdx.x;
    const int wid  = tid >> 5;
    const int lane = tid & 31;

    const uint4* __restrict__ Ag = reinterpret_cast<const uint4*>(
        g_qcat + ((size_t)bh * kS + i0) * kKC);
    const uint4* __restrict__ Kg = reinterpret_cast<const uint4*>(
        g_kcat + (size_t)bh * kS * kKC);

    // Prologue: stage A + B tile 0 (group 0), B tile 1 (group 1).
    #pragma unroll
    for (int r = 0; r < 4; ++r) {
        const int f   = tid + r * 256;
        const int row = f >> 3;
        const int c16 = f & 7;
        const uint32_t off = SW128((uint32_t)(row * 128 + c16 * 16));
        cp_async16(sAu + off, Ag + row * 8 + c16);
        cp_async16(sBu[0] + off, Kg + (size_t)row * 8 + c16);
    }
    cp_commit();
    #pragma unroll
    for (int r = 0; r < 4; ++r) {
        const int f   = tid + r * 256;
        const int row = f >> 3;
        const int c16 = f & 7;
        const uint32_t off = SW128((uint32_t)(row * 128 + c16 * 16));
        cp_async16(sBu[1] + off, Kg + (size_t)(128 + row) * 8 + c16);
    }
    cp_commit();

    const int wm = wid & 3;            // 4 warps cover 128 rows
    const int wn = wid >> 2;           // 2 warps cover 128 cols
    const int imb = wm * 32;
    const int jnb = wn * 64;
    const int g  = lane >> 2;
    const int tg = lane & 3;

    #pragma unroll 1
    for (int jt = 0; jt < kNT; ++jt) {
        const uint32_t sB = sBu[jt % 3];
        const int j0 = jt * 128;

        // Prefetch tile jt+2 (overwrites buffer last read in iter jt-1,
        // protected by the trailing __syncthreads of that iteration).
        if (jt + 2 < kNT) {
            #pragma unroll
            for (int r = 0; r < 4; ++r) {
                const int f   = tid + r * 256;
                const int row = f >> 3;
                const int c16 = f & 7;
                const uint32_t off = SW128((uint32_t)(row * 128 + c16 * 16));
                cp_async16(sBu[(jt + 2) % 3] + off,
                           Kg + (size_t)(j0 + 256 + row) * 8 + c16);
            }
            cp_commit();
        }
        // Ensure tile jt's group has landed.
        if (jt + 2 < kNT)      cp_wait_group<2>();
        else if (jt + 1 < kNT) cp_wait_group<1>();
        else                   cp_wait_group<0>();
        __syncthreads();

        float acc[2][8][4];
        #pragma unroll
        for (int mt = 0; mt < 2; ++mt)
            #pragma unroll
            for (int nt = 0; nt < 8; ++nt)
                #pragma unroll
                for (int e = 0; e < 4; ++e) acc[mt][nt][e] = 0.0f;

        // Fragment-reuse mainloop: kk in {0,16}; A hi at kk, A lo at kk+32.
        #pragma unroll
        for (int kk = 0; kk < 32; kk += 16) {
            uint32_t afh[2][4], afl[2][4];
            #pragma unroll
            for (int mt = 0; mt < 2; ++mt) {
                const int row = imb + mt * 16 + (lane & 15);
                const int chkh = (kk >> 3) + (lane >> 4);
                const int chkl = ((kk + 32) >> 3) + (lane >> 4);
                ldsm_x4(afh[mt], sAu + SW128((uint32_t)(row * 128 + chkh * 16)));
                ldsm_x4(afl[mt], sAu + SW128((uint32_t)(row * 128 + chkl * 16)));
            }
            #pragma unroll
            for (int half = 0; half < 2; ++half) {
                uint32_t bfh[4][2], bfl[4][2];
                #pragma unroll
                for (int np = 0; np < 2; ++np) {
                    const int row = jnb + half * 32 + np * 16
                                  + (lane & 7) + ((lane & 16) >> 1);
                    const int chkh = (kk >> 3) + ((lane >> 3) & 1);
                    const int chkl = ((kk + 32) >> 3) + ((lane >> 3) & 1);
                    uint32_t r4[4];
                    ldsm_x4(r4, sB + SW128((uint32_t)(row * 128 + chkh * 16)));
                    bfh[np * 2 + 0][0] = r4[0]; bfh[np * 2 + 0][1] = r4[1];
                    bfh[np * 2 + 1][0] = r4[2]; bfh[np * 2 + 1][1] = r4[3];
                    ldsm_x4(r4, sB + SW128((uint32_t)(row * 128 + chkl * 16)));
                    bfl[np * 2 + 0][0] = r4[0]; bfl[np * 2 + 0][1] = r4[1];
                    bfl[np * 2 + 1][0] = r4[2]; bfl[np * 2 + 1][1] = r4[3];
                }
                #pragma unroll
                for (int mt = 0; mt < 2; ++mt)
                    #pragma unroll
                    for (int nt4 = 0; nt4 < 4; ++nt4) {
                        float* a = acc[mt][half * 4 + nt4];
                        mma_bf16(a, afh[mt], bfh[nt4]);   // hi.hi
                        mma_bf16(a, afl[mt], bfh[nt4]);   // lo.hi
                        mma_bf16(a, afh[mt], bfl[nt4]);   // hi.lo
                    }
            }
        }

        // Epilogue: store scores + per-tile row maxes (2 gmem slots per tile)
        float2* __restrict__ Sbase = reinterpret_cast<float2*>(
            g_s + ((size_t)bh * kS + i0) * kS + j0);

        #pragma unroll
        for (int mt = 0; mt < 2; ++mt) {
            const int r0 = imb + mt * 16 + g;
            float rm0 = -FLT_MAX, rm1 = -FLT_MAX;
            #pragma unroll
            for (int nt = 0; nt < 8; ++nt) {
                const int c2 = (jnb + nt * 8 + tg * 2) >> 1;
                float2 lo = make_float2(acc[mt][nt][0], acc[mt][nt][1]);
                float2 hi = make_float2(acc[mt][nt][2], acc[mt][nt][3]);
                Sbase[(size_t)r0 * (kS / 2) + c2]       = lo;
                Sbase[(size_t)(r0 + 8) * (kS / 2) + c2] = hi;
                rm0 = fmaxf(rm0, fmaxf(lo.x, lo.y));
                rm1 = fmaxf(rm1, fmaxf(hi.x, hi.y));
            }
            rm0 = fmaxf(rm0, __shfl_xor_sync(0xffffffffu, rm0, 1));
            rm0 = fmaxf(rm0, __shfl_xor_sync(0xffffffffu, rm0, 2));
            rm1 = fmaxf(rm1, __shfl_xor_sync(0xffffffffu, rm1, 1));
            rm1 = fmaxf(rm1, __shfl_xor_sync(0xffffffffu, rm1, 2));
            if (tg == 0) {
                const size_t rowg = (size_t)bh * kS + i0 + r0;
                g_tmax2[(rowg * kNT + jt) * 2 + wn]       = rm0;
                g_tmax2[((rowg + 8) * kNT + jt) * 2 + wn] = rm1;
            }
        }

        __syncthreads();   // all warps done with buffer jt%3 before reuse
    }
}

// ---------------------------------------------------------------------------
// Exact slow fallback for a row whose candidate list overflowed (rare):
// reads the DENSE stored scores (cheap), Michelot + ballot-pop AV.
// ---------------------------------------------------------------------------
__device__ __noinline__ float slow_row(const float4* __restrict__ S4,
                                       const float* __restrict__ Vbh,
                                       float thr, int lane)
{
    float tau = thr;
    int prev = -1;
    for (int it = 0; it < 200; ++it) {
        float sum = 0.0f; int cnt = 0;
        for (int c = lane; c < kS / 4; c += 32) {
            float4 v = __ldg(S4 + c);
            if (v.x > tau) { sum += v.x; ++cnt; }
            if (v.y > tau) { sum += v.y; ++cnt; }
            if (v.z > tau) { sum += v.z; ++cnt; }
            if (v.w > tau) { sum += v.w; ++cnt; }
        }
        #pragma unroll
        for (int o = 16; o; o >>= 1) {
            sum += __shfl_xor_sync(0xffffffffu, sum, o);
            cnt += __shfl_xor_sync(0xffffffffu, cnt, o);
        }
        if (cnt == prev || cnt == 0) break;
        tau = (sum - 1.0f) / (float)cnt;
        prev = cnt;
    }
    float a = 0.0f;
    for (int c = lane; c < kS / 4; c += 32) {
        float4 v = __ldg(S4 + c);
        const float vv[4] = {v.x, v.y, v.z, v.w};
        #pragma unroll
        for (int e = 0; e < 4; ++e) {
            float w = vv[e] - tau;
            unsigned mk = __ballot_sync(0xffffffffu, w > 0.0f);
            while (mk) {
                int b = __ffs(mk) - 1;
                mk &= mk - 1;
                float wb = __shfl_sync(0xffffffffu, w, b);
                int jj = __shfl_sync(0xffffffffu, c * 4 + e, b);
                a = fmaf(wb, __ldg(Vbh + jj * kDK + lane), a);
            }
        }
    }
    return a;
}

// ---------------------------------------------------------------------------
// Kernel 3 — sparsemax + AV, tile-selective. 1 warp per query row.
// Reads 16x2 tilemax slots -> exact row max -> scans only hot tiles.
// ---------------------------------------------------------------------------
__global__ __launch_bounds__(256, 2)
void sparsemax_av(float* __restrict__ out)
{
    __shared__ float2 Lists[8][kCap];

    const int bh   = blockIdx.y;
    const int warp = threadIdx.x >> 5;
    const int lane = threadIdx.x & 31;
    const unsigned lmask = (1u << lane) - 1u;
    const int qi   = blockIdx.x * 8 + warp;
    const size_t rowg = (size_t)bh * kS + qi;

    const float4* __restrict__ S4 =
        reinterpret_cast<const float4*>(g_s + rowg * kS);
    const float* __restrict__ Vbh = g_v + bh * kS * kDK;

    // Row max from the 16 tile maxes (2 slots each; exact)
    float tm = -FLT_MAX;
    if (lane < kNT) {
        const float t0 = __ldg(g_tmax2 + (rowg * kNT + lane) * 2);
        const float t1 = __ldg(g_tmax2 + (rowg * kNT + lane) * 2 + 1);
        tm = fmaxf(t0, t1);
    }
    float m = tm;
    #pragma unroll
    for (int o = 16; o; o >>= 1)
        m = fmaxf(m, __shfl_xor_sync(0xffffffffu, m, o));
    const float thr = m - 1.0f;
    unsigned tmask = __ballot_sync(0xffffffffu, lane < kNT && tm > thr);

    // Candidate compaction over selected 128-col tiles only
    float2* __restrict__ Lq = Lists[warp];
    int n = 0;
    unsigned it = tmask;
    while (it && n <= kCap) {
        const int t = __ffs(it) - 1;
        it &= it - 1;
        float4 v = __ldg(S4 + t * 32 + lane);
        const int jb = t * 128 + lane * 4;
        const float vv[4] = {v.x, v.y, v.z, v.w};
        #pragma unroll
        for (int e = 0; e < 4; ++e) {
            const bool cand = vv[e] > thr;
            const unsigned mk = __ballot_sync(0xffffffffu, cand);
            if (mk) {
                const int idx = n + __popc(mk & lmask);
                if (cand && idx < kCap)
                    Lq[idx] = make_float2(vv[e], __int_as_float(jb + e));
                n += __popc(mk);
            }
        }
    }
    __syncwarp();

    float a;
    if (n <= kCap) {
        float c0 = (lane      < n) ? Lq[lane     ].x : -FLT_MAX;
        float c1 = (lane + 32 < n) ? Lq[lane + 32].x : -FLT_MAX;
        float c2 = (lane + 64 < n) ? Lq[lane + 64].x : -FLT_MAX;
        float c3 = (lane + 96 < n) ? Lq[lane + 96].x : -FLT_MAX;
        float tau = thr;
        int prev = -1;
        for (int iter = 0; iter < 80; ++iter) {
            float sum = 0.0f; int cnt = 0;
            if (c0 > tau) { sum += c0; ++cnt; }
            if (c1 > tau) { sum += c1; ++cnt; }
            if (c2 > tau) { sum += c2; ++cnt; }
            if (c3 > tau) { sum += c3; ++cnt; }
            #pragma unroll
            for (int o = 16; o; o >>= 1) {
                sum += __shfl_xor_sync(0xffffffffu, sum, o);
                cnt += __shfl_xor_sync(0xffffffffu, cnt, o);
            }
            if (cnt == prev || cnt == 0) break;
            tau = (sum - 1.0f) / (float)cnt;
            prev = cnt;
        }
        float a0 = 0.0f, a1 = 0.0f;
        int ci = 0;
        for (; ci + 2 <= n; ci += 2) {
            float2 p0 = Lq[ci], p1 = Lq[ci + 1];
            float w0 = fmaxf(p0.x - tau, 0.0f);
            float w1 = fmaxf(p1.x - tau, 0.0f);
            a0 = fmaf(w0, __ldg(Vbh + __float_as_int(p0.y) * kDK + lane), a0);
            a1 = fmaf(w1, __ldg(Vbh + __float_as_int(p1.y) * kDK + lane), a1);
        }
        if (ci < n) {
            float2 p = Lq[ci];
            float w = fmaxf(p.x - tau, 0.0f);
            a0 = fmaf(w, __ldg(Vbh + __float_as_int(p.y) * kDK + lane), a0);
        }
        a = a0 + a1;
    } else {
        a = slow_row(S4, Vbh, thr, lane);
    }

    const int bb = bh >> 3;
    const int h  = bh & 7;
    out[(bb * kS + qi) * kDM + h * kDK + lane] = a;
}

// ---------------------------------------------------------------------------
extern "C" void kernel_launch(void* const* d_in, const int* in_sizes, int n_in,
                              void* d_out, int out_size)
{
    const float* query = (const float*)d_in[0];
    const float* key   = (const float*)d_in[1];
    const float* value = (const float*)d_in[2];
    const float* Wq    = (const float*)d_in[3];
    const float* bq    = (const float*)d_in[4];
    const float* Wk    = (const float*)d_in[5];
    const float* bk    = (const float*)d_in[6];
    const float* Wv    = (const float*)d_in[7];
    const float* bv    = (const float*)d_in[8];
    float* out = (float*)d_out;

    dim3 pgrid(kDM / 64, kNRow / 128, 3);      // (4, 32, 3)
    proj_kernel<<<pgrid, 256>>>(query, key, value, Wq, bq, Wk, bk, Wv, bv);

    cudaFuncSetAttribute(score_gemm_tc,
                         cudaFuncAttributeMaxDynamicSharedMemorySize, kSmemScore);
    dim3 sgrid(1, kS / 128, kB * kH);          // (1, 16, 16) = 256 CTAs
    score_gemm_tc<<<sgrid, 256, kSmemScore>>>();

    dim3 agrid(kS / 8, kB * kH);               // (256, 16)
    sparsemax_av<<<agrid, 256>>>(out);

    (void)in_sizes; (void)n_in; (void)out_size;
}